// round 11
// baseline (speedup 1.0000x reference)
#include <cuda_runtime.h>

// ---------------- scratch (no allocations allowed) ----------------
__device__ __align__(16) float g_attn[4 * 1024 * 16 * 8];  // [B,S,H,8]  2MB
__device__ __align__(16) float g_wt[128 * 128];            // W transposed [e][j]

// GAMMA^2 = log2(e)/sqrt(8); dot of GAMMA-scaled vectors = score*log2(e) directly.
#define GAMMA     0.7142163217f
#define INV_GAMMA 1.4001353259f

// ---------------- f32x2 packed helpers (Blackwell dual-FMA pipe) ----------------
typedef unsigned long long u64;

__device__ __forceinline__ u64 f2mul(u64 a, u64 b) {
    u64 d; asm("mul.rn.f32x2 %0, %1, %2;" : "=l"(d) : "l"(a), "l"(b)); return d;
}
__device__ __forceinline__ u64 f2add(u64 a, u64 b) {
    u64 d; asm("add.rn.f32x2 %0, %1, %2;" : "=l"(d) : "l"(a), "l"(b)); return d;
}
__device__ __forceinline__ u64 f2fma(u64 a, u64 b, u64 c) {
    u64 d; asm("fma.rn.f32x2 %0, %1, %2, %3;" : "=l"(d) : "l"(a), "l"(b), "l"(c)); return d;
}
__device__ __forceinline__ u64 f2pack(float lo, float hi) {
    u64 d; asm("mov.b64 %0, {%1, %2};" : "=l"(d) : "f"(lo), "f"(hi)); return d;
}
__device__ __forceinline__ void f2unpack(u64 v, float& lo, float& hi) {
    asm("mov.b64 {%0, %1}, %2;" : "=f"(lo), "=f"(hi) : "l"(v));
}
__device__ __forceinline__ u64 f2bcast(float x) { return f2pack(x, x); }

// MUFU exp2 — separate pipe, fully overlapped with the FMA stream here.
__device__ __forceinline__ float ex2_fast(float y) {
    float r; asm("ex2.approx.ftz.f32 %0, %1;" : "=f"(r) : "f"(y)); return r;
}

// ---------------- attention (qkv computed in-block, analytically) ----------------
// Circuit identity: every RX(p_w) commutes backward to the front (wire w is only
// ever the TARGET of the single CNOT it must cross; RX = exp(-i theta X/2)
// commutes with controlled-X on its target), giving a product state with
// theta_w = x_w + p_w, followed by the pure CNOT ladder = classical XOR
// permutation b'_0 = b1^..^b7, b'_v = b0^..^bv. Independent bits => Z-expectations
//   z_0 = prod_{w=1..7} cos(theta_w),  z_v = prod_{w=0..v} cos(theta_w)  (v>=1)
//
// Grid (17, 64): x in [0,16) = 64-query attention tiles (1024 blocks, 6.92/SM,
// ~1% wave tail); x == 16 = 64 blocks that transpose W into g_wt (folded launch).
// 128 threads (4 warps -> all 4 SMSPs regardless of the wid%4 scheduler mapping).
// Split-KV: 2 threads per query; threads 0..63 process keys [0,512), threads
// 64..127 process keys [512,1024); partials merged through smem at the end.
// Scores bounded (|s| <= 8/sqrt(8) = 2.83) -> plain sum-of-exp merge, no max.
// NOTE: __launch_bounds__(128,7) caps registers at 73/thread; the mainloop
// unroll is kept at 2 so the live set stays safely under that cap (no spills).
__global__ void __launch_bounds__(128, 7) attn_kernel(const float* __restrict__ x,
                                                      const float* __restrict__ rxp,
                                                      const float* __restrict__ w) {
    __shared__ __align__(16) float kv[1024 * 8];  // 32KB: full K(=V=Q) tile for this bh
    int tid = threadIdx.x;

    if (blockIdx.x == 16) {  // W-transpose lane: 64 blocks x 128 threads x 2 elems
        int base = blockIdx.y * 256 + tid;
#pragma unroll
        for (int i = 0; i < 2; i++) {
            int idx = base + 128 * i;       // coalesced read of w
            int j = idx >> 7, e = idx & 127;
            g_wt[e * 128 + j] = w[idx];
        }
        return;  // uniform for the whole block: no barrier divergence
    }

    int bh = blockIdx.y;
    int b = bh >> 4, h = bh & 15;

    float p0 = rxp[0], p1 = rxp[1], p2 = rxp[2], p3 = rxp[3];
    float p4 = rxp[4], p5 = rxp[5], p6 = rxp[6], p7 = rxp[7];

    // ---- prologue: build the GAMMA-scaled qkv tile for this (b,h) in smem ----
#pragma unroll
    for (int i = 0; i < 8; i++) {
        int s = tid + 128 * i;
        const float4* xr = (const float4*)(x + ((((b << 10) + s) * 16 + h) << 3));
        float4 x0 = xr[0], x1 = xr[1];

        float t0 = __cosf(x0.x + p0);
        float t1 = __cosf(x0.y + p1);
        float t2 = __cosf(x0.z + p2);
        float t3 = __cosf(x0.w + p3);
        float t4 = __cosf(x1.x + p4);
        float t5 = __cosf(x1.y + p5);
        float t6 = __cosf(x1.z + p6);
        float t7 = __cosf(x1.w + p7);

        t1 *= GAMMA;  // every output contains t1 -> folds the attention pre-scale in

        float z1 = t0 * t1;
        float z2 = z1 * t2;
        float z3 = z2 * t3;
        float z4 = z3 * t4;
        float z5 = z4 * t5;
        float z6 = z5 * t6;
        float z7 = z6 * t7;
        float z0 = t1 * t2;
        z0 *= t3; z0 *= t4; z0 *= t5; z0 *= t6; z0 *= t7;

        float4* o = (float4*)(kv + (s << 3));
        o[0] = make_float4(z0, z1, z2, z3);
        o[1] = make_float4(z4, z5, z6, z7);
    }
    __syncthreads();

    // ---- mainloop: 2 threads per query, 512 keys each, 2 keys per iteration ----
    int qi = tid & 63;                    // query within tile
    int r = blockIdx.x * 64 + qi;         // query row
    int kbase = (tid >> 6) << 9;          // 0 or 512
    const ulonglong2* kvp = (const ulonglong2*)kv;
    ulonglong2 qa = kvp[2 * r], qb = kvp[2 * r + 1];
    u64 q01 = qa.x, q23 = qa.y, q45 = qb.x, q67 = qb.y;

    u64 a01 = 0ull, a23 = 0ull, a45 = 0ull, a67 = 0ull;
    u64 den2 = 0ull;  // packed (den_even, den_odd)

#pragma unroll 2
    for (int jj = 0; jj < 512; jj += 2) {
        int j = kbase + jj;
        ulonglong2 ka0 = kvp[2 * j];      // broadcast LDS.128 (half-warp same addr)
        ulonglong2 kb0 = kvp[2 * j + 1];
        ulonglong2 ka1 = kvp[2 * j + 2];
        ulonglong2 kb1 = kvp[2 * j + 3];

        // packed dots for key j (t0) and key j+1 (t1), sharing q registers
        u64 t0 = f2mul(q01, ka0.x);
        u64 t1 = f2mul(q01, ka1.x);
        t0 = f2fma(q23, ka0.y, t0);
        t1 = f2fma(q23, ka1.y, t1);
        t0 = f2fma(q45, kb0.x, t0);
        t1 = f2fma(q45, kb1.x, t1);
        t0 = f2fma(q67, kb0.y, t0);
        t1 = f2fma(q67, kb1.y, t1);

        // transpose-pack: one f2add performs both horizontal adds -> y = (s0, s1)
        float d0l, d0h, d1l, d1h;
        f2unpack(t0, d0l, d0h);
        f2unpack(t1, d1l, d1h);
        u64 y = f2add(f2pack(d0l, d1l), f2pack(d0h, d1h));

        // MUFU exp2 (y = score * log2(e) via GAMMA prescale, |y| <= ~4.2)
        float y0, y1;
        f2unpack(y, y0, y1);
        float e0 = ex2_fast(y0);
        float e1 = ex2_fast(y1);

        den2 = f2add(den2, f2pack(e0, e1));  // one add updates both denominators
        u64 ee0 = f2bcast(e0);
        u64 ee1 = f2bcast(e1);
        a01 = f2fma(ee0, ka0.x, a01);
        a23 = f2fma(ee0, ka0.y, a23);
        a45 = f2fma(ee0, kb0.x, a45);
        a67 = f2fma(ee0, kb0.y, a67);
        a01 = f2fma(ee1, ka1.x, a01);
        a23 = f2fma(ee1, ka1.y, a23);
        a45 = f2fma(ee1, kb1.x, a45);
        a67 = f2fma(ee1, kb1.y, a67);
    }

    float dl, dh;
    f2unpack(den2, dl, dh);
    float den = dl + dh;

    float o0, o1, o2, o3, o4, o5, o6, o7;
    f2unpack(a01, o0, o1);
    f2unpack(a23, o2, o3);
    f2unpack(a45, o4, o5);
    f2unpack(a67, o6, o7);

    // ---- merge the two key-halves (kv reused as scratch; stride 9 is coprime
    //      with 32 banks -> conflict-free scalar access) ----
    __syncthreads();  // all kv reads complete before overwrite
    if (tid >= 64) {
        float* sc = kv + (tid - 64) * 9;
        sc[0] = den;
        sc[1] = o0; sc[2] = o1; sc[3] = o2; sc[4] = o3;
        sc[5] = o4; sc[6] = o5; sc[7] = o6; sc[8] = o7;
    }
    __syncthreads();
    if (tid < 64) {
        const float* sc = kv + tid * 9;
        den += sc[0];
        o0 += sc[1]; o1 += sc[2]; o2 += sc[3]; o3 += sc[4];
        o4 += sc[5]; o5 += sc[6]; o6 += sc[7]; o7 += sc[8];

        float inv = __fdividef(INV_GAMMA, den);  // undo GAMMA scaling of V
        float4* out4 = (float4*)g_attn + ((((b << 10) + r) * 16 + h) << 1);
        out4[0] = make_float4(o0 * inv, o1 * inv, o2 * inv, o3 * inv);
        out4[1] = make_float4(o4 * inv, o5 * inv, o6 * inv, o7 * inv);
    }
}

// ---------------- combine: out[4096,128] = attn[4096,128] @ W^T ----------------
__global__ void __launch_bounds__(256) combine_kernel(float* __restrict__ out) {
    __shared__ __align__(16) float sA[32 * 128];  // 16KB A tile
    const float* A = g_attn + blockIdx.x * 4096;
    int tid = threadIdx.x;
#pragma unroll
    for (int i = 0; i < 4; i++)
        ((float4*)sA)[tid + 256 * i] = ((const float4*)A)[tid + 256 * i];
    __syncthreads();

    int j = tid & 127;
    int r0 = tid >> 7;  // 0 or 1; thread owns rows r0, r0+2, ..., r0+30
    float acc[16];
#pragma unroll
    for (int i = 0; i < 16; i++) acc[i] = 0.f;

    for (int e = 0; e < 128; e++) {
        float wv = __ldg(&g_wt[e * 128 + j]);  // coalesced, L1/L2 resident
#pragma unroll
        for (int i = 0; i < 16; i++)
            acc[i] = fmaf(sA[(r0 + 2 * i) * 128 + e], wv, acc[i]);  // broadcast LDS
    }

    int rowbase = blockIdx.x * 32 + r0;
#pragma unroll
    for (int i = 0; i < 16; i++)
        out[(rowbase + 2 * i) * 128 + j] = acc[i];
}

// ---------------- launch ----------------
extern "C" void kernel_launch(void* const* d_in, const int* in_sizes, int n_in,
                              void* d_out, int out_size) {
    const float* x   = (const float*)d_in[0];  // [4,1024,128]
    const float* rxp = (const float*)d_in[1];  // [8]
    const float* w   = (const float*)d_in[2];  // [128,128]
    float* out = (float*)d_out;                // [4,1024,128]

    attn_kernel<<<dim3(17, 64), 128>>>(x, rxp, w);  // attn tiles + folded W-transpose
    combine_kernel<<<128, 256>>>(out);
}